// round 12
// baseline (speedup 1.0000x reference)
#include <cuda_runtime.h>
#include <cuda_bf16.h>
#include <cstdint>

constexpr int Nn = 16384, Ee = 524288;

// ---- scratch (device globals; allocs forbidden) ----
__device__ __nv_bfloat16 g_Tbf[64 * Nn];     // (X@W)^T in bf16, [64][Nn] K-major
__device__ float g_H1[Nn * 64];
__device__ float g_H2[Nn * 64];
__device__ float g_U[Nn * 256];
__device__ float g_V[Nn * 256];

// ---- Tbf[n][r] = bf16( sum_k X[r][k] * W[k][n] ), K in {128, 64}, 64 outputs ----
template <int K>
__global__ void __launch_bounds__(256)
k_xw(const float* __restrict__ X, const float* __restrict__ W, __nv_bfloat16* __restrict__ Tbf) {
    __shared__ float Ws[K * 64];
    const int tid = threadIdx.x;
    for (int i = tid; i < K * 64; i += 256) Ws[i] = W[i];
    __syncthreads();
    const int r = blockIdx.x * 256 + tid;
    float acc[64];
    #pragma unroll
    for (int n = 0; n < 64; n++) acc[n] = 0.f;
    const float4* xr = (const float4*)(X + (size_t)r * K);
    #pragma unroll 4
    for (int k4 = 0; k4 < K / 4; k4++) {
        float4 xv = __ldg(xr + k4);
        float xs[4] = {xv.x, xv.y, xv.z, xv.w};
        #pragma unroll
        for (int u = 0; u < 4; u++) {
            const float* wk = &Ws[(k4 * 4 + u) * 64];
            #pragma unroll
            for (int n = 0; n < 64; n++) acc[n] = fmaf(xs[u], wk[n], acc[n]);
        }
    }
    #pragma unroll
    for (int n = 0; n < 64; n++) Tbf[(size_t)n * Nn + r] = __float2bfloat16(acc[n]);
}

// ---- GEMM: H[16384,64] = sigmoid(A_fp32[16384,16384] @ Tbf^T + bias) ----
// A streamed as fp32 via cp.async, converted to bf16 in-register for mma.sync.
constexpr int MT = 128, KC = 64, ST = 4, NIT = Nn / KC;
constexpr int ASf = 72;                       // A smem row stride (floats) -> 288 B
constexpr int BSe = 72;                       // B smem row stride (bf16)   -> 144 B
constexpr int A_BYTES = 128 * ASf * 4;        // 36864
constexpr int B_BYTES = 64 * BSe * 2;         // 9216
constexpr int STG_B = A_BYTES + B_BYTES;      // 46080
constexpr int SMEM_DYN = ST * STG_B;          // 184320

__device__ __forceinline__ uint32_t cvt2(float2 p) {
    uint32_t r;
    asm("cvt.rn.bf16x2.f32 %0, %1, %2;" : "=r"(r) : "f"(p.y), "f"(p.x));
    return r;
}

__device__ __forceinline__ void ld_stage(const float* __restrict__ Af,
                                         const __nv_bfloat16* __restrict__ Bt,
                                         char* sm, int m0, int it, int tid) {
    const int k0 = it * KC;
    const uint32_t sb = (uint32_t)__cvta_generic_to_shared(sm + (it % ST) * STG_B);
    #pragma unroll
    for (int i = 0; i < 10; i++) {
        const int f = i * 256 + tid;          // 16B chunks: A 2048, B 512
        uint32_t dst;
        const void* src;
        if (f < 2048) {
            const int r = f >> 4, c = f & 15;
            src = Af + (size_t)(m0 + r) * Nn + k0 + c * 4;
            dst = sb + (uint32_t)(r * 288 + c * 16);
        } else {
            const int f2 = f - 2048;
            const int n = f2 >> 3, c = f2 & 7;
            src = Bt + (size_t)n * Nn + k0 + c * 8;
            dst = sb + (uint32_t)(A_BYTES + n * 144 + c * 16);
        }
        asm volatile("cp.async.cg.shared.global [%0], [%1], 16;" :: "r"(dst), "l"(src) : "memory");
    }
}

__global__ void __launch_bounds__(256, 1)
gemm_f32a_sig(const float* __restrict__ Af, const __nv_bfloat16* __restrict__ Bt,
              const float* __restrict__ bias, float* __restrict__ H) {
    extern __shared__ char smem[];
    const int tid = threadIdx.x, wid = tid >> 5, lane = tid & 31;
    const int wm = wid >> 1, wn = wid & 1;    // warps 4(M) x 2(N)
    const int ln4 = lane >> 2, lm4 = lane & 3;
    const int m0 = blockIdx.x * MT;

    float c[2][4][4];
    #pragma unroll
    for (int a = 0; a < 2; a++)
        #pragma unroll
        for (int b = 0; b < 4; b++)
            #pragma unroll
            for (int q = 0; q < 4; q++) c[a][b][q] = 0.f;

    #pragma unroll
    for (int s = 0; s < ST - 1; s++) {
        ld_stage(Af, Bt, smem, m0, s, tid);
        asm volatile("cp.async.commit_group;" ::: "memory");
    }

    for (int it = 0; it < NIT; it++) {
        asm volatile("cp.async.wait_group 2;" ::: "memory");
        __syncthreads();
        const float* Asm = (const float*)(smem + (it % ST) * STG_B);
        const __nv_bfloat16* Bsm = (const __nv_bfloat16*)(smem + (it % ST) * STG_B + A_BYTES);
        #pragma unroll
        for (int ks = 0; ks < 4; ks++) {
            const int kb = ks * 16 + lm4 * 2;
            uint32_t a[2][4], bf[4][2];
            #pragma unroll
            for (int mt = 0; mt < 2; mt++) {
                const float* ap = Asm + (wm * 32 + mt * 16 + ln4) * ASf + kb;
                a[mt][0] = cvt2(*(const float2*)ap);
                a[mt][1] = cvt2(*(const float2*)(ap + 8 * ASf));
                a[mt][2] = cvt2(*(const float2*)(ap + 8));
                a[mt][3] = cvt2(*(const float2*)(ap + 8 * ASf + 8));
            }
            #pragma unroll
            for (int nt = 0; nt < 4; nt++) {
                const __nv_bfloat16* bp = Bsm + (wn * 32 + nt * 8 + ln4) * BSe + kb;
                bf[nt][0] = *(const uint32_t*)bp;
                bf[nt][1] = *(const uint32_t*)(bp + 8);
            }
            #pragma unroll
            for (int mt = 0; mt < 2; mt++)
                #pragma unroll
                for (int nt = 0; nt < 4; nt++)
                    asm volatile(
                        "mma.sync.aligned.m16n8k16.row.col.f32.bf16.bf16.f32 "
                        "{%0,%1,%2,%3}, {%4,%5,%6,%7}, {%8,%9}, {%0,%1,%2,%3};"
                        : "+f"(c[mt][nt][0]), "+f"(c[mt][nt][1]),
                          "+f"(c[mt][nt][2]), "+f"(c[mt][nt][3])
                        : "r"(a[mt][0]), "r"(a[mt][1]), "r"(a[mt][2]), "r"(a[mt][3]),
                          "r"(bf[nt][0]), "r"(bf[nt][1]));
        }
        if (it + ST - 1 < NIT) ld_stage(Af, Bt, smem, m0, it + ST - 1, tid);
        asm volatile("cp.async.commit_group;" ::: "memory");
    }

    // epilogue: bias + sigmoid, fp32 out
    #pragma unroll
    for (int mt = 0; mt < 2; mt++)
        #pragma unroll
        for (int nt = 0; nt < 4; nt++) {
            const int col = wn * 32 + nt * 8 + lm4 * 2;
            const float b0 = __ldg(bias + col), b1 = __ldg(bias + col + 1);
            #pragma unroll
            for (int h = 0; h < 2; h++) {
                const int row = m0 + wm * 32 + mt * 16 + ln4 + h * 8;
                const float x0 = c[mt][nt][2 * h] + b0, x1 = c[mt][nt][2 * h + 1] + b1;
                *(float2*)(H + (size_t)row * 64 + col) =
                    make_float2(1.f / (1.f + __expf(-x0)), 1.f / (1.f + __expf(-x1)));
            }
        }
}

// ---- u = H2 @ Wd[0:64], v = H2 @ Wd[64:128] ----
__global__ void __launch_bounds__(256)
k4_uv(const float* __restrict__ H2, const float* __restrict__ Wd,
      float* __restrict__ U, float* __restrict__ V) {
    __shared__ float Hs[32 * 65];
    const int tid = threadIdx.x, r0 = blockIdx.x * 32;
    for (int i = tid; i < 32 * 64; i += 256)
        Hs[(i >> 6) * 65 + (i & 63)] = H2[(size_t)(r0 + (i >> 6)) * 64 + (i & 63)];
    __syncthreads();
    const int rl = tid >> 3, c0 = (tid & 7) * 32;
    float au[32], av[32];
    #pragma unroll
    for (int q = 0; q < 32; q++) { au[q] = 0.f; av[q] = 0.f; }
    for (int j = 0; j < 64; j++) {
        const float h = Hs[rl * 65 + j];
        const float4* wu = (const float4*)(Wd + (size_t)j * 256 + c0);
        const float4* wv = (const float4*)(Wd + (size_t)(64 + j) * 256 + c0);
        #pragma unroll
        for (int q = 0; q < 8; q++) {
            float4 a = __ldg(wu + q);
            au[4*q+0] = fmaf(h, a.x, au[4*q+0]); au[4*q+1] = fmaf(h, a.y, au[4*q+1]);
            au[4*q+2] = fmaf(h, a.z, au[4*q+2]); au[4*q+3] = fmaf(h, a.w, au[4*q+3]);
            float4 b = __ldg(wv + q);
            av[4*q+0] = fmaf(h, b.x, av[4*q+0]); av[4*q+1] = fmaf(h, b.y, av[4*q+1]);
            av[4*q+2] = fmaf(h, b.z, av[4*q+2]); av[4*q+3] = fmaf(h, b.w, av[4*q+3]);
        }
    }
    float4* uo = (float4*)(U + (size_t)(r0 + rl) * 256 + c0);
    float4* vo = (float4*)(V + (size_t)(r0 + rl) * 256 + c0);
    #pragma unroll
    for (int q = 0; q < 8; q++) {
        uo[q] = make_float4(au[4*q], au[4*q+1], au[4*q+2], au[4*q+3]);
        vo[q] = make_float4(av[4*q], av[4*q+1], av[4*q+2], av[4*q+3]);
    }
}

// ---- per-edge: softmax(relu(u[i]+v[j]+bd) @ Wo + bo) * mask  (1 warp / edge) ----
__global__ void __launch_bounds__(256)
edge_k(const int* __restrict__ eg, const int* __restrict__ msk,
       const float* __restrict__ U, const float* __restrict__ V,
       const float* __restrict__ bd, const float* __restrict__ Wo,
       const float* __restrict__ bo, float* __restrict__ out) {
    const int e = blockIdx.x * 8 + (threadIdx.x >> 5);
    const int lane = threadIdx.x & 31;
    const int i = __ldg(&eg[2 * e]), j = __ldg(&eg[2 * e + 1]);
    const float4* up = (const float4*)(U + (size_t)i * 256) + lane * 2;
    const float4* vp = (const float4*)(V + (size_t)j * 256) + lane * 2;
    const float4* bp = (const float4*)bd + lane * 2;
    float z0 = 0.f, z1 = 0.f;
    #pragma unroll
    for (int q = 0; q < 2; q++) {
        float4 u = __ldg(up + q), v = __ldg(vp + q), b = __ldg(bp + q);
        const int cc = lane * 8 + q * 4;
        float s;
        s = fmaxf(u.x + v.x + b.x, 0.f); z0 = fmaf(s, __ldg(&Wo[2*cc+0]), z0); z1 = fmaf(s, __ldg(&Wo[2*cc+1]), z1);
        s = fmaxf(u.y + v.y + b.y, 0.f); z0 = fmaf(s, __ldg(&Wo[2*cc+2]), z0); z1 = fmaf(s, __ldg(&Wo[2*cc+3]), z1);
        s = fmaxf(u.z + v.z + b.z, 0.f); z0 = fmaf(s, __ldg(&Wo[2*cc+4]), z0); z1 = fmaf(s, __ldg(&Wo[2*cc+5]), z1);
        s = fmaxf(u.w + v.w + b.w, 0.f); z0 = fmaf(s, __ldg(&Wo[2*cc+6]), z0); z1 = fmaf(s, __ldg(&Wo[2*cc+7]), z1);
    }
    #pragma unroll
    for (int o = 16; o; o >>= 1) {
        z0 += __shfl_xor_sync(0xFFFFFFFFu, z0, o);
        z1 += __shfl_xor_sync(0xFFFFFFFFu, z1, o);
    }
    if (lane == 0) {
        z0 += __ldg(&bo[0]); z1 += __ldg(&bo[1]);
        const float m = fmaxf(z0, z1);
        const float e0 = __expf(z0 - m), e1 = __expf(z1 - m);
        const float inv = 1.f / (e0 + e1);
        const float fm = (float)__ldg(&msk[e]);
        ((float2*)out)[e] = make_float2(e0 * inv * fm, e1 * inv * fm);
    }
}

extern "C" void kernel_launch(void* const* d_in, const int* in_sizes, int n_in,
                              void* d_out, int out_size) {
    const float* X  = (const float*)d_in[0];
    const float* A  = (const float*)d_in[1];
    const int*   eg = (const int*)d_in[2];
    const int*   mk = (const int*)d_in[3];
    const float* W1 = (const float*)d_in[4];
    const float* b1 = (const float*)d_in[5];
    const float* W2 = (const float*)d_in[6];
    const float* b2 = (const float*)d_in[7];
    const float* Wd = (const float*)d_in[8];
    const float* bd = (const float*)d_in[9];
    const float* Wo = (const float*)d_in[10];
    const float* bo = (const float*)d_in[11];
    float* out = (float*)d_out;

    __nv_bfloat16 *Tbf;
    float *H1, *H2, *U, *V;
    cudaGetSymbolAddress((void**)&Tbf, g_Tbf);
    cudaGetSymbolAddress((void**)&H1, g_H1);
    cudaGetSymbolAddress((void**)&H2, g_H2);
    cudaGetSymbolAddress((void**)&U,  g_U);
    cudaGetSymbolAddress((void**)&V,  g_V);

    cudaFuncSetAttribute(gemm_f32a_sig, cudaFuncAttributeMaxDynamicSharedMemorySize, SMEM_DYN);

    k_xw<128><<<Nn / 256, 256>>>(X, W1, Tbf);
    gemm_f32a_sig<<<Nn / MT, 256, SMEM_DYN>>>(A, Tbf, b1, H1);
    k_xw<64><<<Nn / 256, 256>>>(H1, W2, Tbf);
    gemm_f32a_sig<<<Nn / MT, 256, SMEM_DYN>>>(A, Tbf, b2, H2);
    k4_uv<<<Nn / 32, 256>>>(H2, Wd, U, V);
    edge_k<<<Ee / 8, 256>>>(eg, mk, U, V, bd, Wo, bo, out);
}

// round 13
// speedup vs baseline: 1.2868x; 1.2868x over previous
#include <cuda_runtime.h>
#include <cuda_bf16.h>
#include <cstdint>

constexpr int Nn = 16384, Ee = 524288;

// ---- scratch (device globals; allocs forbidden) ----
__device__ __nv_bfloat16 g_Tbf[64 * Nn];     // (X@W)^T in bf16, [64][Nn] K-major
__device__ float g_H1[Nn * 64];
__device__ float g_H2[Nn * 64];
__device__ float g_U[Nn * 256];
__device__ float g_V[Nn * 256];

// ---- Tbf[n][r] = bf16( sum_k X[r][k] * W[k][n] ), K in {128, 64}, 64 outputs ----
template <int K>
__global__ void __launch_bounds__(256)
k_xw(const float* __restrict__ X, const float* __restrict__ W, __nv_bfloat16* __restrict__ Tbf) {
    __shared__ float Ws[K * 64];
    const int tid = threadIdx.x;
    for (int i = tid; i < K * 64; i += 256) Ws[i] = W[i];
    __syncthreads();
    const int r = blockIdx.x * 256 + tid;
    float acc[64];
    #pragma unroll
    for (int n = 0; n < 64; n++) acc[n] = 0.f;
    const float4* xr = (const float4*)(X + (size_t)r * K);
    #pragma unroll 4
    for (int k4 = 0; k4 < K / 4; k4++) {
        float4 xv = __ldg(xr + k4);
        float xs[4] = {xv.x, xv.y, xv.z, xv.w};
        #pragma unroll
        for (int u = 0; u < 4; u++) {
            const float* wk = &Ws[(k4 * 4 + u) * 64];
            #pragma unroll
            for (int n = 0; n < 64; n++) acc[n] = fmaf(xs[u], wk[n], acc[n]);
        }
    }
    #pragma unroll
    for (int n = 0; n < 64; n++) Tbf[(size_t)n * Nn + r] = __float2bfloat16(acc[n]);
}

// ---- GEMM: H[16384,64] = sigmoid(A_fp32[16384,16384] @ Tbf^T + bias) ----
// 512 threads / 16 warps (4M x 4N) for latency hiding; A fp32 via cp.async,
// converted to bf16 in-register for mma.sync.
constexpr int MT = 128, KC = 64, ST = 4, NIT = Nn / KC;
constexpr int ASf = 72;                       // A smem row stride (floats) -> 288 B
constexpr int BSe = 72;                       // B smem row stride (bf16)   -> 144 B
constexpr int A_BYTES = 128 * ASf * 4;        // 36864
constexpr int B_BYTES = 64 * BSe * 2;         // 9216
constexpr int STG_B = A_BYTES + B_BYTES;      // 46080
constexpr int SMEM_DYN = ST * STG_B;          // 184320

__device__ __forceinline__ uint32_t cvt2(float2 p) {
    uint32_t r;
    asm("cvt.rn.bf16x2.f32 %0, %1, %2;" : "=r"(r) : "f"(p.y), "f"(p.x));
    return r;
}

__device__ __forceinline__ void ld_stage(const float* __restrict__ Af,
                                         const __nv_bfloat16* __restrict__ Bt,
                                         char* sm, int m0, int it, int tid) {
    const int k0 = it * KC;
    const uint32_t sb = (uint32_t)__cvta_generic_to_shared(sm + (it % ST) * STG_B);
    #pragma unroll
    for (int i = 0; i < 5; i++) {
        const int f = i * 512 + tid;          // 16B chunks: A 2048, B 512
        uint32_t dst;
        const void* src;
        if (f < 2048) {
            const int r = f >> 4, c = f & 15;
            src = Af + (size_t)(m0 + r) * Nn + k0 + c * 4;
            dst = sb + (uint32_t)(r * 288 + c * 16);
        } else {
            const int f2 = f - 2048;
            const int n = f2 >> 3, c = f2 & 7;
            src = Bt + (size_t)n * Nn + k0 + c * 8;
            dst = sb + (uint32_t)(A_BYTES + n * 144 + c * 16);
        }
        asm volatile("cp.async.cg.shared.global [%0], [%1], 16;" :: "r"(dst), "l"(src) : "memory");
    }
}

__global__ void __launch_bounds__(512, 1)
gemm_f32a_sig(const float* __restrict__ Af, const __nv_bfloat16* __restrict__ Bt,
              const float* __restrict__ bias, float* __restrict__ H) {
    extern __shared__ char smem[];
    const int tid = threadIdx.x, wid = tid >> 5, lane = tid & 31;
    const int wm = wid >> 2, wn = wid & 3;    // warps 4(M) x 4(N)
    const int ln4 = lane >> 2, lm4 = lane & 3;
    const int m0 = blockIdx.x * MT;

    float c[2][2][4];
    #pragma unroll
    for (int a = 0; a < 2; a++)
        #pragma unroll
        for (int b = 0; b < 2; b++)
            #pragma unroll
            for (int q = 0; q < 4; q++) c[a][b][q] = 0.f;

    #pragma unroll
    for (int s = 0; s < ST - 1; s++) {
        ld_stage(Af, Bt, smem, m0, s, tid);
        asm volatile("cp.async.commit_group;" ::: "memory");
    }

    for (int it = 0; it < NIT; it++) {
        asm volatile("cp.async.wait_group 2;" ::: "memory");
        __syncthreads();
        const float* Asm = (const float*)(smem + (it % ST) * STG_B);
        const __nv_bfloat16* Bsm = (const __nv_bfloat16*)(smem + (it % ST) * STG_B + A_BYTES);
        #pragma unroll
        for (int ks = 0; ks < 4; ks++) {
            const int kb = ks * 16 + lm4 * 2;
            uint32_t a[2][4], bf[2][2];
            #pragma unroll
            for (int mt = 0; mt < 2; mt++) {
                const float* ap = Asm + (wm * 32 + mt * 16 + ln4) * ASf + kb;
                a[mt][0] = cvt2(*(const float2*)ap);
                a[mt][1] = cvt2(*(const float2*)(ap + 8 * ASf));
                a[mt][2] = cvt2(*(const float2*)(ap + 8));
                a[mt][3] = cvt2(*(const float2*)(ap + 8 * ASf + 8));
            }
            #pragma unroll
            for (int nt = 0; nt < 2; nt++) {
                const __nv_bfloat16* bp = Bsm + (wn * 16 + nt * 8 + ln4) * BSe + kb;
                bf[nt][0] = *(const uint32_t*)bp;
                bf[nt][1] = *(const uint32_t*)(bp + 8);
            }
            #pragma unroll
            for (int mt = 0; mt < 2; mt++)
                #pragma unroll
                for (int nt = 0; nt < 2; nt++)
                    asm volatile(
                        "mma.sync.aligned.m16n8k16.row.col.f32.bf16.bf16.f32 "
                        "{%0,%1,%2,%3}, {%4,%5,%6,%7}, {%8,%9}, {%0,%1,%2,%3};"
                        : "+f"(c[mt][nt][0]), "+f"(c[mt][nt][1]),
                          "+f"(c[mt][nt][2]), "+f"(c[mt][nt][3])
                        : "r"(a[mt][0]), "r"(a[mt][1]), "r"(a[mt][2]), "r"(a[mt][3]),
                          "r"(bf[nt][0]), "r"(bf[nt][1]));
        }
        if (it + ST - 1 < NIT) ld_stage(Af, Bt, smem, m0, it + ST - 1, tid);
        asm volatile("cp.async.commit_group;" ::: "memory");
    }

    // epilogue: bias + sigmoid, fp32 out
    #pragma unroll
    for (int mt = 0; mt < 2; mt++)
        #pragma unroll
        for (int nt = 0; nt < 2; nt++) {
            const int col = wn * 16 + nt * 8 + lm4 * 2;
            const float b0 = __ldg(bias + col), b1 = __ldg(bias + col + 1);
            #pragma unroll
            for (int h = 0; h < 2; h++) {
                const int row = m0 + wm * 32 + mt * 16 + ln4 + h * 8;
                const float x0 = c[mt][nt][2 * h] + b0, x1 = c[mt][nt][2 * h + 1] + b1;
                *(float2*)(H + (size_t)row * 64 + col) =
                    make_float2(1.f / (1.f + __expf(-x0)), 1.f / (1.f + __expf(-x1)));
            }
        }
}

// ---- u = H2 @ Wd[0:64], v = H2 @ Wd[64:128] ----
__global__ void __launch_bounds__(256)
k4_uv(const float* __restrict__ H2, const float* __restrict__ Wd,
      float* __restrict__ U, float* __restrict__ V) {
    __shared__ float Hs[32 * 65];
    const int tid = threadIdx.x, r0 = blockIdx.x * 32;
    for (int i = tid; i < 32 * 64; i += 256)
        Hs[(i >> 6) * 65 + (i & 63)] = H2[(size_t)(r0 + (i >> 6)) * 64 + (i & 63)];
    __syncthreads();
    const int rl = tid >> 3, c0 = (tid & 7) * 32;
    float au[32], av[32];
    #pragma unroll
    for (int q = 0; q < 32; q++) { au[q] = 0.f; av[q] = 0.f; }
    for (int j = 0; j < 64; j++) {
        const float h = Hs[rl * 65 + j];
        const float4* wu = (const float4*)(Wd + (size_t)j * 256 + c0);
        const float4* wv = (const float4*)(Wd + (size_t)(64 + j) * 256 + c0);
        #pragma unroll
        for (int q = 0; q < 8; q++) {
            float4 a = __ldg(wu + q);
            au[4*q+0] = fmaf(h, a.x, au[4*q+0]); au[4*q+1] = fmaf(h, a.y, au[4*q+1]);
            au[4*q+2] = fmaf(h, a.z, au[4*q+2]); au[4*q+3] = fmaf(h, a.w, au[4*q+3]);
            float4 b = __ldg(wv + q);
            av[4*q+0] = fmaf(h, b.x, av[4*q+0]); av[4*q+1] = fmaf(h, b.y, av[4*q+1]);
            av[4*q+2] = fmaf(h, b.z, av[4*q+2]); av[4*q+3] = fmaf(h, b.w, av[4*q+3]);
        }
    }
    float4* uo = (float4*)(U + (size_t)(r0 + rl) * 256 + c0);
    float4* vo = (float4*)(V + (size_t)(r0 + rl) * 256 + c0);
    #pragma unroll
    for (int q = 0; q < 8; q++) {
        uo[q] = make_float4(au[4*q], au[4*q+1], au[4*q+2], au[4*q+3]);
        vo[q] = make_float4(av[4*q], av[4*q+1], av[4*q+2], av[4*q+3]);
    }
}

// ---- per-edge: softmax(relu(u[i]+v[j]+bd) @ Wo + bo) * mask ----
// Persistent grid-stride, 1 warp/edge. Each lane OWNS channels [lane*8, lane*8+8):
// its Wo (16 floats) and bd (8 floats) are loop-invariant -> hoisted to registers.
// Per edge: only 4 coalesced LDG.128 (u,v rows) + FMAs + shfl reduce.
__global__ void __launch_bounds__(256)
edge_k(const int* __restrict__ eg, const int* __restrict__ msk,
       const float* __restrict__ U, const float* __restrict__ V,
       const float* __restrict__ bd, const float* __restrict__ Wo,
       const float* __restrict__ bo, float* __restrict__ out) {
    const int lane = threadIdx.x & 31;
    const int warp0 = (blockIdx.x * blockDim.x + threadIdx.x) >> 5;
    const int nwarp = (gridDim.x * blockDim.x) >> 5;
    const int c0 = lane * 8;

    // hoisted per-lane constants
    float4 wo[4];                              // Wo pairs for channels c0..c0+7
    #pragma unroll
    for (int q = 0; q < 4; q++) wo[q] = __ldg((const float4*)Wo + lane * 4 + q);
    float bdv[8];
    #pragma unroll
    for (int q = 0; q < 2; q++) {
        float4 b = __ldg((const float4*)bd + lane * 2 + q);
        bdv[4*q+0] = b.x; bdv[4*q+1] = b.y; bdv[4*q+2] = b.z; bdv[4*q+3] = b.w;
    }
    const float bo0 = __ldg(&bo[0]), bo1 = __ldg(&bo[1]);

    for (int e = warp0; e < Ee; e += nwarp) {
        const int i = __ldg(&eg[2 * e]), j = __ldg(&eg[2 * e + 1]);
        const float4* up = (const float4*)(U + (size_t)i * 256 + c0);
        const float4* vp = (const float4*)(V + (size_t)j * 256 + c0);
        float z0 = 0.f, z1 = 0.f;
        #pragma unroll
        for (int q = 0; q < 2; q++) {
            const float4 u = __ldg(up + q), v = __ldg(vp + q);
            float s;
            s = fmaxf(u.x + v.x + bdv[4*q+0], 0.f);
            z0 = fmaf(s, wo[2*q].x, z0);   z1 = fmaf(s, wo[2*q].y, z1);
            s = fmaxf(u.y + v.y + bdv[4*q+1], 0.f);
            z0 = fmaf(s, wo[2*q].z, z0);   z1 = fmaf(s, wo[2*q].w, z1);
            s = fmaxf(u.z + v.z + bdv[4*q+2], 0.f);
            z0 = fmaf(s, wo[2*q+1].x, z0); z1 = fmaf(s, wo[2*q+1].y, z1);
            s = fmaxf(u.w + v.w + bdv[4*q+3], 0.f);
            z0 = fmaf(s, wo[2*q+1].z, z0); z1 = fmaf(s, wo[2*q+1].w, z1);
        }
        #pragma unroll
        for (int o = 16; o; o >>= 1) {
            z0 += __shfl_xor_sync(0xFFFFFFFFu, z0, o);
            z1 += __shfl_xor_sync(0xFFFFFFFFu, z1, o);
        }
        if (lane == 0) {
            const float d = (z0 + bo0) - (z1 + bo1);
            const float p0 = 1.f / (1.f + __expf(-d));     // softmax over 2 logits
            const float fm = (float)__ldg(&msk[e]);
            ((float2*)out)[e] = make_float2(p0 * fm, (1.f - p0) * fm);
        }
    }
}

extern "C" void kernel_launch(void* const* d_in, const int* in_sizes, int n_in,
                              void* d_out, int out_size) {
    const float* X  = (const float*)d_in[0];
    const float* A  = (const float*)d_in[1];
    const int*   eg = (const int*)d_in[2];
    const int*   mk = (const int*)d_in[3];
    const float* W1 = (const float*)d_in[4];
    const float* b1 = (const float*)d_in[5];
    const float* W2 = (const float*)d_in[6];
    const float* b2 = (const float*)d_in[7];
    const float* Wd = (const float*)d_in[8];
    const float* bd = (const float*)d_in[9];
    const float* Wo = (const float*)d_in[10];
    const float* bo = (const float*)d_in[11];
    float* out = (float*)d_out;

    __nv_bfloat16 *Tbf;
    float *H1, *H2, *U, *V;
    cudaGetSymbolAddress((void**)&Tbf, g_Tbf);
    cudaGetSymbolAddress((void**)&H1, g_H1);
    cudaGetSymbolAddress((void**)&H2, g_H2);
    cudaGetSymbolAddress((void**)&U,  g_U);
    cudaGetSymbolAddress((void**)&V,  g_V);

    cudaFuncSetAttribute(gemm_f32a_sig, cudaFuncAttributeMaxDynamicSharedMemorySize, SMEM_DYN);

    k_xw<128><<<Nn / 256, 256>>>(X, W1, Tbf);
    gemm_f32a_sig<<<Nn / MT, 512, SMEM_DYN>>>(A, Tbf, b1, H1);
    k_xw<64><<<Nn / 256, 256>>>(H1, W2, Tbf);
    gemm_f32a_sig<<<Nn / MT, 512, SMEM_DYN>>>(A, Tbf, b2, H2);
    k4_uv<<<Nn / 32, 256>>>(H2, Wd, U, V);
    edge_k<<<592, 256>>>(eg, mk, U, V, bd, Wo, bo, out);
}

// round 14
// speedup vs baseline: 1.9808x; 1.5393x over previous
#include <cuda_runtime.h>
#include <cuda_bf16.h>
#include <cstdint>

constexpr int Nn = 16384, Ee = 524288;

// ---- scratch (device globals; allocs forbidden) ----
__device__ __nv_bfloat16 g_Tbf[64 * Nn];     // (X@W)^T in bf16, [64][Nn] K-major
__device__ float g_H1[Nn * 64];
__device__ float g_H2[Nn * 64];
__device__ float g_U[Nn * 256];
__device__ float g_V[Nn * 256];

// ---- Tbf[n][r] = bf16( sum_k X[r][k] * W[k][n] ), K in {128, 64} ----
template <int K>
__global__ void __launch_bounds__(256)
k_xw(const float* __restrict__ X, const float* __restrict__ W, __nv_bfloat16* __restrict__ Tbf) {
    __shared__ float Ws[K * 64];
    const int tid = threadIdx.x;
    for (int i = tid; i < K * 64; i += 256) Ws[i] = W[i];
    __syncthreads();
    const int r = blockIdx.x * 256 + tid;
    float acc[64];
    #pragma unroll
    for (int n = 0; n < 64; n++) acc[n] = 0.f;
    const float4* xr = (const float4*)(X + (size_t)r * K);
    #pragma unroll 4
    for (int k4 = 0; k4 < K / 4; k4++) {
        float4 xv = __ldg(xr + k4);
        float xs[4] = {xv.x, xv.y, xv.z, xv.w};
        #pragma unroll
        for (int u = 0; u < 4; u++) {
            const float* wk = &Ws[(k4 * 4 + u) * 64];
            #pragma unroll
            for (int n = 0; n < 64; n++) acc[n] = fmaf(xs[u], wk[n], acc[n]);
        }
    }
    #pragma unroll
    for (int n = 0; n < 64; n++) Tbf[(size_t)n * Nn + r] = __float2bfloat16(acc[n]);
}

// ---- GEMM: H = sigmoid(A_fp32 @ Tbf^T + bias) ----
// A: LDG.128 -> cvt to bf16 in-register -> STS (bf16 smem, halves smem traffic).
// 256 threads, 8 warps 4M x 2N (minimal frag redundancy), 2-stage double buffer.
constexpr int MT = 128, KC = 64, NIT = Nn / KC;
constexpr int ASB = 144;                       // smem row stride bytes (72 bf16)
constexpr int A_SMB = 128 * ASB;               // 18432
constexpr int B_SMB = 64 * ASB;                // 9216
constexpr int STGB = A_SMB + B_SMB;            // 27648
constexpr int SMEM_G = 2 * STGB;               // 55296

__device__ __forceinline__ uint32_t cvt2(float lo, float hi) {
    uint32_t r;
    asm("cvt.rn.bf16x2.f32 %0, %1, %2;" : "=r"(r) : "f"(hi), "f"(lo));
    return r;
}

__global__ void __launch_bounds__(256, 1)
gemm2(const float* __restrict__ Af, const __nv_bfloat16* __restrict__ Bt,
      const float* __restrict__ bias, float* __restrict__ H) {
    extern __shared__ char smem[];
    const int tid = threadIdx.x, wid = tid >> 5, lane = tid & 31;
    const int wm = wid >> 1, wn = wid & 1;     // 4M x 2N
    const int ln4 = lane >> 2, lm4 = lane & 3;
    const int m0 = blockIdx.x * MT;

    float4 fa[8];                              // A staging: 8 x 16B = row of 4 floats each
    uint4  fb[2];                              // B staging

    // per-thread load/store mappings (fixed across iters)
    const int ar[8] = { tid >> 4, (256 + tid) >> 4, (512 + tid) >> 4, (768 + tid) >> 4,
                        (1024 + tid) >> 4, (1280 + tid) >> 4, (1536 + tid) >> 4, (1792 + tid) >> 4 };
    const int ac = tid & 15;
    const int bn[2] = { tid >> 3, (256 + tid) >> 3 };
    const int bc = tid & 7;

    float c[2][4][4];
    #pragma unroll
    for (int a = 0; a < 2; a++)
        #pragma unroll
        for (int b = 0; b < 4; b++)
            #pragma unroll
            for (int q = 0; q < 4; q++) c[a][b][q] = 0.f;

    // prologue: load iter 0
    {
        const int k0 = 0;
        #pragma unroll
        for (int i = 0; i < 8; i++)
            fa[i] = __ldg((const float4*)(Af + (size_t)(m0 + ar[i]) * Nn + k0 + ac * 4));
        #pragma unroll
        for (int i = 0; i < 2; i++)
            fb[i] = __ldg((const uint4*)(Bt + (size_t)bn[i] * Nn + k0 + bc * 8));
    }

    for (int it = 0; it < NIT; it++) {
        char* stg = smem + (it & 1) * STGB;
        // store staged tiles (A converted to bf16)
        #pragma unroll
        for (int i = 0; i < 8; i++) {
            uint2 p;
            p.x = cvt2(fa[i].x, fa[i].y);
            p.y = cvt2(fa[i].z, fa[i].w);
            *(uint2*)(stg + ar[i] * ASB + ac * 8) = p;
        }
        #pragma unroll
        for (int i = 0; i < 2; i++)
            *(uint4*)(stg + A_SMB + bn[i] * ASB + bc * 16) = fb[i];
        __syncthreads();

        // prefetch next iter into regs (hidden under compute)
        if (it + 1 < NIT) {
            const int k0 = (it + 1) * KC;
            #pragma unroll
            for (int i = 0; i < 8; i++)
                fa[i] = __ldg((const float4*)(Af + (size_t)(m0 + ar[i]) * Nn + k0 + ac * 4));
            #pragma unroll
            for (int i = 0; i < 2; i++)
                fb[i] = __ldg((const uint4*)(Bt + (size_t)bn[i] * Nn + k0 + bc * 8));
        }

        const char* As = stg;
        const char* Bs = stg + A_SMB;
        #pragma unroll
        for (int ks = 0; ks < 4; ks++) {
            const int kbB = ks * 32 + lm4 * 4;     // byte offset of 2 bf16
            uint32_t a[2][4], bf[4][2];
            #pragma unroll
            for (int mt = 0; mt < 2; mt++) {
                const char* ap = As + (wm * 32 + mt * 16 + ln4) * ASB + kbB;
                a[mt][0] = *(const uint32_t*)ap;
                a[mt][1] = *(const uint32_t*)(ap + 8 * ASB);
                a[mt][2] = *(const uint32_t*)(ap + 16);
                a[mt][3] = *(const uint32_t*)(ap + 8 * ASB + 16);
            }
            #pragma unroll
            for (int nt = 0; nt < 4; nt++) {
                const char* bp = Bs + (wn * 32 + nt * 8 + ln4) * ASB + kbB;
                bf[nt][0] = *(const uint32_t*)bp;
                bf[nt][1] = *(const uint32_t*)(bp + 16);
            }
            #pragma unroll
            for (int mt = 0; mt < 2; mt++)
                #pragma unroll
                for (int nt = 0; nt < 4; nt++)
                    asm volatile(
                        "mma.sync.aligned.m16n8k16.row.col.f32.bf16.bf16.f32 "
                        "{%0,%1,%2,%3}, {%4,%5,%6,%7}, {%8,%9}, {%0,%1,%2,%3};"
                        : "+f"(c[mt][nt][0]), "+f"(c[mt][nt][1]),
                          "+f"(c[mt][nt][2]), "+f"(c[mt][nt][3])
                        : "r"(a[mt][0]), "r"(a[mt][1]), "r"(a[mt][2]), "r"(a[mt][3]),
                          "r"(bf[nt][0]), "r"(bf[nt][1]));
        }
        // single sync per iter is safe: stsA(it+2) (same buffer as it) can only
        // execute after sync(it+1), which laggards reach only after compute(it).
    }

    // epilogue: bias + sigmoid
    #pragma unroll
    for (int mt = 0; mt < 2; mt++)
        #pragma unroll
        for (int nt = 0; nt < 4; nt++) {
            const int col = wn * 32 + nt * 8 + lm4 * 2;
            const float b0 = __ldg(bias + col), b1 = __ldg(bias + col + 1);
            #pragma unroll
            for (int h = 0; h < 2; h++) {
                const int row = m0 + wm * 32 + mt * 16 + ln4 + h * 8;
                const float x0 = c[mt][nt][2 * h] + b0, x1 = c[mt][nt][2 * h + 1] + b1;
                *(float2*)(H + (size_t)row * 64 + col) =
                    make_float2(1.f / (1.f + __expf(-x0)), 1.f / (1.f + __expf(-x1)));
            }
        }
}

// ---- u = H2 @ Wd[0:64], v = H2 @ Wd[64:128]; Wd + H staged in smem ----
// Block: 64 rows, 2 batches of 32. Thread owns output cols {q*32 + (tid&7)*4 .. +3}
// -> every Wd LDS.128 is bank-conflict-free (lanes 0..7 hit banks 4l..4l+3).
constexpr int HS = 68;                         // Hs row stride (floats)
constexpr int SMEM_UV = 128 * 256 * 4 + 64 * HS * 4;   // 131072 + 17408 = 148480

__global__ void __launch_bounds__(256, 1)
k4_uv(const float* __restrict__ H2, const float* __restrict__ Wd,
      float* __restrict__ U, float* __restrict__ V) {
    extern __shared__ float sm[];
    float* Wds = sm;                           // [128][256]
    float* Hs  = sm + 128 * 256;               // [64][HS]
    const int tid = threadIdx.x, r0 = blockIdx.x * 64;

    for (int i = tid; i < 128 * 64; i += 256)  // 8192 float4 chunks
        *(float4*)(Wds + i * 4) = __ldg((const float4*)Wd + i);
    for (int i = tid; i < 64 * 16; i += 256) { // H tile: 64 rows x 16 float4
        const int r = i >> 4, cq = i & 15;
        *(float4*)(Hs + r * HS + cq * 4) = __ldg((const float4*)(H2 + (size_t)(r0 + r) * 64) + cq);
    }
    __syncthreads();

    const int cl = (tid & 7) * 4;              // lane column base
    #pragma unroll
    for (int b = 0; b < 2; b++) {
        const int rl = b * 32 + (tid >> 3);
        float au[32], av[32];
        #pragma unroll
        for (int q = 0; q < 32; q++) { au[q] = 0.f; av[q] = 0.f; }
        for (int j = 0; j < 64; j++) {
            const float hu = Hs[rl * HS + j];
            const float* wu = Wds + j * 256;
            const float* wv = Wds + (64 + j) * 256;
            #pragma unroll
            for (int q = 0; q < 8; q++) {
                const float4 a = *(const float4*)(wu + q * 32 + cl);
                au[4*q+0] = fmaf(hu, a.x, au[4*q+0]); au[4*q+1] = fmaf(hu, a.y, au[4*q+1]);
                au[4*q+2] = fmaf(hu, a.z, au[4*q+2]); au[4*q+3] = fmaf(hu, a.w, au[4*q+3]);
                const float4 v = *(const float4*)(wv + q * 32 + cl);
                av[4*q+0] = fmaf(hu, v.x, av[4*q+0]); av[4*q+1] = fmaf(hu, v.y, av[4*q+1]);
                av[4*q+2] = fmaf(hu, v.z, av[4*q+2]); av[4*q+3] = fmaf(hu, v.w, av[4*q+3]);
            }
        }
        float* uo = U + (size_t)(r0 + rl) * 256;
        float* vo = V + (size_t)(r0 + rl) * 256;
        #pragma unroll
        for (int q = 0; q < 8; q++) {
            *(float4*)(uo + q * 32 + cl) = make_float4(au[4*q], au[4*q+1], au[4*q+2], au[4*q+3]);
            *(float4*)(vo + q * 32 + cl) = make_float4(av[4*q], av[4*q+1], av[4*q+2], av[4*q+3]);
        }
    }
}

// ---- per-edge: softmax(relu(u[i]+v[j]+bd) @ Wo + bo) * mask ----
// Warp per edge, 2 edges per loop iter. Only d = z0 - z1 is reduced (softmax of
// 2 logits). Per-lane Wo-diff and bd hoisted to registers.
__global__ void __launch_bounds__(256)
edge_k(const int* __restrict__ eg, const int* __restrict__ msk,
       const float* __restrict__ U, const float* __restrict__ V,
       const float* __restrict__ bd, const float* __restrict__ Wo,
       const float* __restrict__ bo, float* __restrict__ out) {
    const int lane = threadIdx.x & 31;
    const int warp0 = (blockIdx.x * blockDim.x + threadIdx.x) >> 5;
    const int nwarp = (gridDim.x * blockDim.x) >> 5;
    const int c0 = lane * 8;

    float wd[8], bdv[8];
    #pragma unroll
    for (int q = 0; q < 4; q++) {
        const float4 w = __ldg((const float4*)Wo + lane * 4 + q);  // pairs (w0,w1)x2
        wd[2*q]   = w.x - w.y;
        wd[2*q+1] = w.z - w.w;
    }
    #pragma unroll
    for (int q = 0; q < 2; q++) {
        const float4 b = __ldg((const float4*)bd + lane * 2 + q);
        bdv[4*q+0] = b.x; bdv[4*q+1] = b.y; bdv[4*q+2] = b.z; bdv[4*q+3] = b.w;
    }
    const float dbo = __ldg(&bo[0]) - __ldg(&bo[1]);

    for (int e = warp0 * 2; e < Ee; e += nwarp * 2) {
        const int4 ij = __ldg((const int4*)(eg + 2 * e));          // i0,j0,i1,j1
        const float4* u0 = (const float4*)(U + (size_t)ij.x * 256 + c0);
        const float4* v0 = (const float4*)(V + (size_t)ij.y * 256 + c0);
        const float4* u1 = (const float4*)(U + (size_t)ij.z * 256 + c0);
        const float4* v1 = (const float4*)(V + (size_t)ij.w * 256 + c0);
        float d0 = 0.f, d1 = 0.f;
        #pragma unroll
        for (int q = 0; q < 2; q++) {
            const float4 a0 = __ldg(u0 + q), b0v = __ldg(v0 + q);
            const float4 a1 = __ldg(u1 + q), b1v = __ldg(v1 + q);
            float s;
            s = fmaxf(a0.x + b0v.x + bdv[4*q+0], 0.f); d0 = fmaf(s, wd[4*q+0], d0);
            s = fmaxf(a0.y + b0v.y + bdv[4*q+1], 0.f); d0 = fmaf(s, wd[4*q+1], d0);
            s = fmaxf(a0.z + b0v.z + bdv[4*q+2], 0.f); d0 = fmaf(s, wd[4*q+2], d0);
            s = fmaxf(a0.w + b0v.w + bdv[4*q+3], 0.f); d0 = fmaf(s, wd[4*q+3], d0);
            s = fmaxf(a1.x + b1v.x + bdv[4*q+0], 0.f); d1 = fmaf(s, wd[4*q+0], d1);
            s = fmaxf(a1.y + b1v.y + bdv[4*q+1], 0.f); d1 = fmaf(s, wd[4*q+1], d1);
            s = fmaxf(a1.z + b1v.z + bdv[4*q+2], 0.f); d1 = fmaf(s, wd[4*q+2], d1);
            s = fmaxf(a1.w + b1v.w + bdv[4*q+3], 0.f); d1 = fmaf(s, wd[4*q+3], d1);
        }
        #pragma unroll
        for (int o = 16; o; o >>= 1) {
            d0 += __shfl_xor_sync(0xFFFFFFFFu, d0, o);
            d1 += __shfl_xor_sync(0xFFFFFFFFu, d1, o);
        }
        if (lane == 0) {
            const float p0 = 1.f / (1.f + __expf(-(d0 + dbo)));
            const float p1 = 1.f / (1.f + __expf(-(d1 + dbo)));
            const float m0 = (float)__ldg(&msk[e]);
            const float m1 = (float)__ldg(&msk[e + 1]);
            float4 o4;
            o4.x = p0 * m0; o4.y = (1.f - p0) * m0;
            o4.z = p1 * m1; o4.w = (1.f - p1) * m1;
            *(float4*)(out + 2 * e) = o4;
        }
    }
}

extern "C" void kernel_launch(void* const* d_in, const int* in_sizes, int n_in,
                              void* d_out, int out_size) {
    const float* X  = (const float*)d_in[0];
    const float* A  = (const float*)d_in[1];
    const int*   eg = (const int*)d_in[2];
    const int*   mk = (const int*)d_in[3];
    const float* W1 = (const float*)d_in[4];
    const float* b1 = (const float*)d_in[5];
    const float* W2 = (const float*)d_in[6];
    const float* b2 = (const float*)d_in[7];
    const float* Wd = (const float*)d_in[8];
    const float* bd = (const float*)d_in[9];
    const float* Wo = (const float*)d_in[10];
    const float* bo = (const float*)d_in[11];
    float* out = (float*)d_out;

    __nv_bfloat16 *Tbf;
    float *H1, *H2, *U, *V;
    cudaGetSymbolAddress((void**)&Tbf, g_Tbf);
    cudaGetSymbolAddress((void**)&H1, g_H1);
    cudaGetSymbolAddress((void**)&H2, g_H2);
    cudaGetSymbolAddress((void**)&U,  g_U);
    cudaGetSymbolAddress((void**)&V,  g_V);

    cudaFuncSetAttribute(gemm2, cudaFuncAttributeMaxDynamicSharedMemorySize, SMEM_G);
    cudaFuncSetAttribute(k4_uv, cudaFuncAttributeMaxDynamicSharedMemorySize, SMEM_UV);

    k_xw<128><<<Nn / 256, 256>>>(X, W1, Tbf);
    gemm2<<<Nn / MT, 256, SMEM_G>>>(A, Tbf, b1, H1);
    k_xw<64><<<Nn / 256, 256>>>(H1, W2, Tbf);
    gemm2<<<Nn / MT, 256, SMEM_G>>>(A, Tbf, b2, H2);
    k4_uv<<<Nn / 64, 256, SMEM_UV>>>(H2, Wd, U, V);
    edge_k<<<592, 256>>>(eg, mk, U, V, bd, Wo, bo, out);
}

// round 15
// speedup vs baseline: 2.3209x; 1.1717x over previous
#include <cuda_runtime.h>
#include <cuda_bf16.h>
#include <cstdint>

constexpr int Nn = 16384, Ee = 524288;

// ---- scratch (device globals; allocs forbidden) ----
__device__ __nv_bfloat16 g_Tbf[64 * Nn];     // (X@W)^T in bf16, [64][Nn] K-major
__device__ float g_H1[Nn * 64];
__device__ float g_H2[Nn * 64];
__device__ float g_U[Nn * 256];
__device__ float g_V[Nn * 256];

// ---- Tbf[n][r] = bf16( sum_k X[r][k] * W[k][n] ), K in {128, 64} ----
template <int K>
__global__ void __launch_bounds__(256)
k_xw(const float* __restrict__ X, const float* __restrict__ W, __nv_bfloat16* __restrict__ Tbf) {
    __shared__ float Ws[K * 64];
    const int tid = threadIdx.x;
    for (int i = tid; i < K * 64; i += 256) Ws[i] = W[i];
    __syncthreads();
    const int r = blockIdx.x * 256 + tid;
    float acc[64];
    #pragma unroll
    for (int n = 0; n < 64; n++) acc[n] = 0.f;
    const float4* xr = (const float4*)(X + (size_t)r * K);
    #pragma unroll 4
    for (int k4 = 0; k4 < K / 4; k4++) {
        float4 xv = __ldg(xr + k4);
        float xs[4] = {xv.x, xv.y, xv.z, xv.w};
        #pragma unroll
        for (int u = 0; u < 4; u++) {
            const float* wk = &Ws[(k4 * 4 + u) * 64];
            #pragma unroll
            for (int n = 0; n < 64; n++) acc[n] = fmaf(xs[u], wk[n], acc[n]);
        }
    }
    #pragma unroll
    for (int n = 0; n < 64; n++) Tbf[(size_t)n * Nn + r] = __float2bfloat16(acc[n]);
}

// ---- GEMM: H = sigmoid(A_fp32 @ Tbf^T + bias) ----
// R12-proven cp.async fp32-A pipeline (ST=4), but MT=64 / grid=256 so 2 CTAs
// co-reside per SM: doubled outstanding cp.async + doubled warps for latency.
constexpr int MT = 64, KC = 64, ST = 4, NIT = Nn / KC;
constexpr int ASf = 72;                       // A smem row stride (floats) -> 288 B
constexpr int BSe = 72;                       // B smem row stride (bf16)   -> 144 B
constexpr int A_BYTES = 64 * ASf * 4;         // 18432
constexpr int B_BYTES = 64 * BSe * 2;         // 9216
constexpr int STG_B = A_BYTES + B_BYTES;      // 27648
constexpr int SMEM_DYN = ST * STG_B;          // 110592 (x2 CTA = 216 KB/SM)

__device__ __forceinline__ uint32_t cvt2(float2 p) {
    uint32_t r;
    asm("cvt.rn.bf16x2.f32 %0, %1, %2;" : "=r"(r) : "f"(p.y), "f"(p.x));
    return r;
}

__device__ __forceinline__ void ld_stage(const float* __restrict__ Af,
                                         const __nv_bfloat16* __restrict__ Bt,
                                         char* sm, int m0, int it, int tid) {
    const int k0 = it * KC;
    const uint32_t sb = (uint32_t)__cvta_generic_to_shared(sm + (it % ST) * STG_B);
    #pragma unroll
    for (int i = 0; i < 6; i++) {
        const int f = i * 256 + tid;          // 16B chunks: A 1024, B 512
        uint32_t dst;
        const void* src;
        if (f < 1024) {
            const int r = f >> 4, c = f & 15;
            src = Af + (size_t)(m0 + r) * Nn + k0 + c * 4;
            dst = sb + (uint32_t)(r * 288 + c * 16);
        } else {
            const int f2 = f - 1024;
            const int n = f2 >> 3, c = f2 & 7;
            src = Bt + (size_t)n * Nn + k0 + c * 8;
            dst = sb + (uint32_t)(A_BYTES + n * 144 + c * 16);
        }
        asm volatile("cp.async.cg.shared.global [%0], [%1], 16;" :: "r"(dst), "l"(src) : "memory");
    }
}

__global__ void __launch_bounds__(256, 2)
gemm_f32a_sig(const float* __restrict__ Af, const __nv_bfloat16* __restrict__ Bt,
              const float* __restrict__ bias, float* __restrict__ H) {
    extern __shared__ char smem[];
    const int tid = threadIdx.x, wid = tid >> 5, lane = tid & 31;
    const int wm = wid >> 1, wn = wid & 1;    // warps 4(M of 16 rows) x 2(N of 32)
    const int ln4 = lane >> 2, lm4 = lane & 3;
    const int m0 = blockIdx.x * MT;

    float c[4][4];
    #pragma unroll
    for (int b = 0; b < 4; b++)
        #pragma unroll
        for (int q = 0; q < 4; q++) c[b][q] = 0.f;

    #pragma unroll
    for (int s = 0; s < ST - 1; s++) {
        ld_stage(Af, Bt, smem, m0, s, tid);
        asm volatile("cp.async.commit_group;" ::: "memory");
    }

    for (int it = 0; it < NIT; it++) {
        asm volatile("cp.async.wait_group 2;" ::: "memory");
        __syncthreads();
        const float* Asm = (const float*)(smem + (it % ST) * STG_B);
        const __nv_bfloat16* Bsm = (const __nv_bfloat16*)(smem + (it % ST) * STG_B + A_BYTES);
        #pragma unroll
        for (int ks = 0; ks < 4; ks++) {
            const int kb = ks * 16 + lm4 * 2;
            uint32_t a[4], bf[4][2];
            {
                const float* ap = Asm + (wm * 16 + ln4) * ASf + kb;
                a[0] = cvt2(*(const float2*)ap);
                a[1] = cvt2(*(const float2*)(ap + 8 * ASf));
                a[2] = cvt2(*(const float2*)(ap + 8));
                a[3] = cvt2(*(const float2*)(ap + 8 * ASf + 8));
            }
            #pragma unroll
            for (int nt = 0; nt < 4; nt++) {
                const __nv_bfloat16* bp = Bsm + (wn * 32 + nt * 8 + ln4) * BSe + kb;
                bf[nt][0] = *(const uint32_t*)bp;
                bf[nt][1] = *(const uint32_t*)(bp + 8);
            }
            #pragma unroll
            for (int nt = 0; nt < 4; nt++)
                asm volatile(
                    "mma.sync.aligned.m16n8k16.row.col.f32.bf16.bf16.f32 "
                    "{%0,%1,%2,%3}, {%4,%5,%6,%7}, {%8,%9}, {%0,%1,%2,%3};"
                    : "+f"(c[nt][0]), "+f"(c[nt][1]), "+f"(c[nt][2]), "+f"(c[nt][3])
                    : "r"(a[0]), "r"(a[1]), "r"(a[2]), "r"(a[3]),
                      "r"(bf[nt][0]), "r"(bf[nt][1]));
        }
        if (it + ST - 1 < NIT) ld_stage(Af, Bt, smem, m0, it + ST - 1, tid);
        asm volatile("cp.async.commit_group;" ::: "memory");
    }

    // epilogue: bias + sigmoid, fp32 out
    #pragma unroll
    for (int nt = 0; nt < 4; nt++) {
        const int col = wn * 32 + nt * 8 + lm4 * 2;
        const float b0 = __ldg(bias + col), b1 = __ldg(bias + col + 1);
        #pragma unroll
        for (int h = 0; h < 2; h++) {
            const int row = m0 + wm * 16 + ln4 + h * 8;
            const float x0 = c[nt][2 * h] + b0, x1 = c[nt][2 * h + 1] + b1;
            *(float2*)(H + (size_t)row * 64 + col) =
                make_float2(1.f / (1.f + __expf(-x0)), 1.f / (1.f + __expf(-x1)));
        }
    }
}

// ---- u = H2 @ Wd[0:64], v = H2 @ Wd[64:128]; Wd + H staged in smem ----
constexpr int HS = 68;
constexpr int SMEM_UV = 128 * 256 * 4 + 64 * HS * 4;   // 148480

__global__ void __launch_bounds__(256, 1)
k4_uv(const float* __restrict__ H2, const float* __restrict__ Wd,
      float* __restrict__ U, float* __restrict__ V) {
    extern __shared__ float sm[];
    float* Wds = sm;                           // [128][256]
    float* Hs  = sm + 128 * 256;               // [64][HS]
    const int tid = threadIdx.x, r0 = blockIdx.x * 64;

    for (int i = tid; i < 128 * 64; i += 256)
        *(float4*)(Wds + i * 4) = __ldg((const float4*)Wd + i);
    for (int i = tid; i < 64 * 16; i += 256) {
        const int r = i >> 4, cq = i & 15;
        *(float4*)(Hs + r * HS + cq * 4) = __ldg((const float4*)(H2 + (size_t)(r0 + r) * 64) + cq);
    }
    __syncthreads();

    const int cl = (tid & 7) * 4;
    #pragma unroll
    for (int b = 0; b < 2; b++) {
        const int rl = b * 32 + (tid >> 3);
        float au[32], av[32];
        #pragma unroll
        for (int q = 0; q < 32; q++) { au[q] = 0.f; av[q] = 0.f; }
        for (int j = 0; j < 64; j++) {
            const float hu = Hs[rl * HS + j];
            const float* wu = Wds + j * 256;
            const float* wv = Wds + (64 + j) * 256;
            #pragma unroll
            for (int q = 0; q < 8; q++) {
                const float4 a = *(const float4*)(wu + q * 32 + cl);
                au[4*q+0] = fmaf(hu, a.x, au[4*q+0]); au[4*q+1] = fmaf(hu, a.y, au[4*q+1]);
                au[4*q+2] = fmaf(hu, a.z, au[4*q+2]); au[4*q+3] = fmaf(hu, a.w, au[4*q+3]);
                const float4 v = *(const float4*)(wv + q * 32 + cl);
                av[4*q+0] = fmaf(hu, v.x, av[4*q+0]); av[4*q+1] = fmaf(hu, v.y, av[4*q+1]);
                av[4*q+2] = fmaf(hu, v.z, av[4*q+2]); av[4*q+3] = fmaf(hu, v.w, av[4*q+3]);
            }
        }
        float* uo = U + (size_t)(r0 + rl) * 256;
        float* vo = V + (size_t)(r0 + rl) * 256;
        #pragma unroll
        for (int q = 0; q < 8; q++) {
            *(float4*)(uo + q * 32 + cl) = make_float4(au[4*q], au[4*q+1], au[4*q+2], au[4*q+3]);
            *(float4*)(vo + q * 32 + cl) = make_float4(av[4*q], av[4*q+1], av[4*q+2], av[4*q+3]);
        }
    }
}

// ---- per-edge: softmax(relu(u[i]+v[j]+bd) @ Wo + bo) * mask ----
__global__ void __launch_bounds__(256)
edge_k(const int* __restrict__ eg, const int* __restrict__ msk,
       const float* __restrict__ U, const float* __restrict__ V,
       const float* __restrict__ bd, const float* __restrict__ Wo,
       const float* __restrict__ bo, float* __restrict__ out) {
    const int lane = threadIdx.x & 31;
    const int warp0 = (blockIdx.x * blockDim.x + threadIdx.x) >> 5;
    const int nwarp = (gridDim.x * blockDim.x) >> 5;
    const int c0 = lane * 8;

    float wd[8], bdv[8];
    #pragma unroll
    for (int q = 0; q < 4; q++) {
        const float4 w = __ldg((const float4*)Wo + lane * 4 + q);
        wd[2*q]   = w.x - w.y;
        wd[2*q+1] = w.z - w.w;
    }
    #pragma unroll
    for (int q = 0; q < 2; q++) {
        const float4 b = __ldg((const float4*)bd + lane * 2 + q);
        bdv[4*q+0] = b.x; bdv[4*q+1] = b.y; bdv[4*q+2] = b.z; bdv[4*q+3] = b.w;
    }
    const float dbo = __ldg(&bo[0]) - __ldg(&bo[1]);

    for (int e = warp0 * 2; e < Ee; e += nwarp * 2) {
        const int4 ij = __ldg((const int4*)(eg + 2 * e));
        const float4* u0 = (const float4*)(U + (size_t)ij.x * 256 + c0);
        const float4* v0 = (const float4*)(V + (size_t)ij.y * 256 + c0);
        const float4* u1 = (const float4*)(U + (size_t)ij.z * 256 + c0);
        const float4* v1 = (const float4*)(V + (size_t)ij.w * 256 + c0);
        float d0 = 0.f, d1 = 0.f;
        #pragma unroll
        for (int q = 0; q < 2; q++) {
            const float4 a0 = __ldg(u0 + q), b0v = __ldg(v0 + q);
            const float4 a1 = __ldg(u1 + q), b1v = __ldg(v1 + q);
            float s;
            s = fmaxf(a0.x + b0v.x + bdv[4*q+0], 0.f); d0 = fmaf(s, wd[4*q+0], d0);
            s = fmaxf(a0.y + b0v.y + bdv[4*q+1], 0.f); d0 = fmaf(s, wd[4*q+1], d0);
            s = fmaxf(a0.z + b0v.z + bdv[4*q+2], 0.f); d0 = fmaf(s, wd[4*q+2], d0);
            s = fmaxf(a0.w + b0v.w + bdv[4*q+3], 0.f); d0 = fmaf(s, wd[4*q+3], d0);
            s = fmaxf(a1.x + b1v.x + bdv[4*q+0], 0.f); d1 = fmaf(s, wd[4*q+0], d1);
            s = fmaxf(a1.y + b1v.y + bdv[4*q+1], 0.f); d1 = fmaf(s, wd[4*q+1], d1);
            s = fmaxf(a1.z + b1v.z + bdv[4*q+2], 0.f); d1 = fmaf(s, wd[4*q+2], d1);
            s = fmaxf(a1.w + b1v.w + bdv[4*q+3], 0.f); d1 = fmaf(s, wd[4*q+3], d1);
        }
        #pragma unroll
        for (int o = 16; o; o >>= 1) {
            d0 += __shfl_xor_sync(0xFFFFFFFFu, d0, o);
            d1 += __shfl_xor_sync(0xFFFFFFFFu, d1, o);
        }
        if (lane == 0) {
            const float p0 = 1.f / (1.f + __expf(-(d0 + dbo)));
            const float p1 = 1.f / (1.f + __expf(-(d1 + dbo)));
            const float m0 = (float)__ldg(&msk[e]);
            const float m1 = (float)__ldg(&msk[e + 1]);
            float4 o4;
            o4.x = p0 * m0; o4.y = (1.f - p0) * m0;
            o4.z = p1 * m1; o4.w = (1.f - p1) * m1;
            *(float4*)(out + 2 * e) = o4;
        }
    }
}

extern "C" void kernel_launch(void* const* d_in, const int* in_sizes, int n_in,
                              void* d_out, int out_size) {
    const float* X  = (const float*)d_in[0];
    const float* A  = (const float*)d_in[1];
    const int*   eg = (const int*)d_in[2];
    const int*   mk = (const int*)d_in[3];
    const float* W1 = (const float*)d_in[4];
    const float* b1 = (const float*)d_in[5];
    const float* W2 = (const float*)d_in[6];
    const float* b2 = (const float*)d_in[7];
    const float* Wd = (const float*)d_in[8];
    const float* bd = (const float*)d_in[9];
    const float* Wo = (const float*)d_in[10];
    const float* bo = (const float*)d_in[11];
    float* out = (float*)d_out;

    __nv_bfloat16 *Tbf;
    float *H1, *H2, *U, *V;
    cudaGetSymbolAddress((void**)&Tbf, g_Tbf);
    cudaGetSymbolAddress((void**)&H1, g_H1);
    cudaGetSymbolAddress((void**)&H2, g_H2);
    cudaGetSymbolAddress((void**)&U,  g_U);
    cudaGetSymbolAddress((void**)&V,  g_V);

    cudaFuncSetAttribute(gemm_f32a_sig, cudaFuncAttributeMaxDynamicSharedMemorySize, SMEM_DYN);
    cudaFuncSetAttribute(k4_uv, cudaFuncAttributeMaxDynamicSharedMemorySize, SMEM_UV);

    k_xw<128><<<Nn / 256, 256>>>(X, W1, Tbf);
    gemm_f32a_sig<<<Nn / MT, 256, SMEM_DYN>>>(A, Tbf, b1, H1);
    k_xw<64><<<Nn / 256, 256>>>(H1, W2, Tbf);
    gemm_f32a_sig<<<Nn / MT, 256, SMEM_DYN>>>(A, Tbf, b2, H2);
    k4_uv<<<Nn / 64, 256, SMEM_UV>>>(H2, Wd, U, V);
    edge_k<<<592, 256>>>(eg, mk, U, V, bd, Wo, bo, out);
}

// round 16
// speedup vs baseline: 2.3513x; 1.0131x over previous
#include <cuda_runtime.h>
#include <cuda_bf16.h>
#include <cstdint>

constexpr int Nn = 16384, Ee = 524288;

// ---- scratch (device globals; allocs forbidden) ----
__device__ __nv_bfloat16 g_Tbf[64 * Nn];     // (X@W)^T in bf16, [64][Nn] K-major
__device__ float g_H1[Nn * 64];
__device__ float g_H2[Nn * 64];
__device__ float g_U[Nn * 256];
__device__ float g_V[Nn * 256];

// ---- Tbf[n][r] = bf16( sum_k X[r][k] * W[k][n] ), K in {128, 64} ----
template <int K>
__global__ void __launch_bounds__(256)
k_xw(const float* __restrict__ X, const float* __restrict__ W, __nv_bfloat16* __restrict__ Tbf) {
    __shared__ float Ws[K * 64];
    const int tid = threadIdx.x;
    for (int i = tid; i < K * 64; i += 256) Ws[i] = W[i];
    __syncthreads();
    const int r = blockIdx.x * 256 + tid;
    float acc[64];
    #pragma unroll
    for (int n = 0; n < 64; n++) acc[n] = 0.f;
    const float4* xr = (const float4*)(X + (size_t)r * K);
    #pragma unroll 4
    for (int k4 = 0; k4 < K / 4; k4++) {
        float4 xv = __ldg(xr + k4);
        float xs[4] = {xv.x, xv.y, xv.z, xv.w};
        #pragma unroll
        for (int u = 0; u < 4; u++) {
            const float* wk = &Ws[(k4 * 4 + u) * 64];
            #pragma unroll
            for (int n = 0; n < 64; n++) acc[n] = fmaf(xs[u], wk[n], acc[n]);
        }
    }
    #pragma unroll
    for (int n = 0; n < 64; n++) Tbf[(size_t)n * Nn + r] = __float2bfloat16(acc[n]);
}

// ---- GEMM: H = sigmoid(A_fp32 @ Tbf^T + bias) ----
// R12-proven cp.async fp32-A pipeline (ST=4), but MT=64 / grid=256 so 2 CTAs
// co-reside per SM: doubled outstanding cp.async + doubled warps for latency.
constexpr int MT = 64, KC = 64, ST = 4, NIT = Nn / KC;
constexpr int ASf = 72;                       // A smem row stride (floats) -> 288 B
constexpr int BSe = 72;                       // B smem row stride (bf16)   -> 144 B
constexpr int A_BYTES = 64 * ASf * 4;         // 18432
constexpr int B_BYTES = 64 * BSe * 2;         // 9216
constexpr int STG_B = A_BYTES + B_BYTES;      // 27648
constexpr int SMEM_DYN = ST * STG_B;          // 110592 (x2 CTA = 216 KB/SM)

__device__ __forceinline__ uint32_t cvt2(float2 p) {
    uint32_t r;
    asm("cvt.rn.bf16x2.f32 %0, %1, %2;" : "=r"(r) : "f"(p.y), "f"(p.x));
    return r;
}

__device__ __forceinline__ void ld_stage(const float* __restrict__ Af,
                                         const __nv_bfloat16* __restrict__ Bt,
                                         char* sm, int m0, int it, int tid) {
    const int k0 = it * KC;
    const uint32_t sb = (uint32_t)__cvta_generic_to_shared(sm + (it % ST) * STG_B);
    #pragma unroll
    for (int i = 0; i < 6; i++) {
        const int f = i * 256 + tid;          // 16B chunks: A 1024, B 512
        uint32_t dst;
        const void* src;
        if (f < 1024) {
            const int r = f >> 4, c = f & 15;
            src = Af + (size_t)(m0 + r) * Nn + k0 + c * 4;
            dst = sb + (uint32_t)(r * 288 + c * 16);
        } else {
            const int f2 = f - 1024;
            const int n = f2 >> 3, c = f2 & 7;
            src = Bt + (size_t)n * Nn + k0 + c * 8;
            dst = sb + (uint32_t)(A_BYTES + n * 144 + c * 16);
        }
        asm volatile("cp.async.cg.shared.global [%0], [%1], 16;" :: "r"(dst), "l"(src) : "memory");
    }
}

__global__ void __launch_bounds__(256, 2)
gemm_f32a_sig(const float* __restrict__ Af, const __nv_bfloat16* __restrict__ Bt,
              const float* __restrict__ bias, float* __restrict__ H) {
    extern __shared__ char smem[];
    const int tid = threadIdx.x, wid = tid >> 5, lane = tid & 31;
    const int wm = wid >> 1, wn = wid & 1;    // warps 4(M of 16 rows) x 2(N of 32)
    const int ln4 = lane >> 2, lm4 = lane & 3;
    const int m0 = blockIdx.x * MT;

    float c[4][4];
    #pragma unroll
    for (int b = 0; b < 4; b++)
        #pragma unroll
        for (int q = 0; q < 4; q++) c[b][q] = 0.f;

    #pragma unroll
    for (int s = 0; s < ST - 1; s++) {
        ld_stage(Af, Bt, smem, m0, s, tid);
        asm volatile("cp.async.commit_group;" ::: "memory");
    }

    for (int it = 0; it < NIT; it++) {
        asm volatile("cp.async.wait_group 2;" ::: "memory");
        __syncthreads();
        const float* Asm = (const float*)(smem + (it % ST) * STG_B);
        const __nv_bfloat16* Bsm = (const __nv_bfloat16*)(smem + (it % ST) * STG_B + A_BYTES);
        #pragma unroll
        for (int ks = 0; ks < 4; ks++) {
            const int kb = ks * 16 + lm4 * 2;
            uint32_t a[4], bf[4][2];
            {
                const float* ap = Asm + (wm * 16 + ln4) * ASf + kb;
                a[0] = cvt2(*(const float2*)ap);
                a[1] = cvt2(*(const float2*)(ap + 8 * ASf));
                a[2] = cvt2(*(const float2*)(ap + 8));
                a[3] = cvt2(*(const float2*)(ap + 8 * ASf + 8));
            }
            #pragma unroll
            for (int nt = 0; nt < 4; nt++) {
                const __nv_bfloat16* bp = Bsm + (wn * 32 + nt * 8 + ln4) * BSe + kb;
                bf[nt][0] = *(const uint32_t*)bp;
                bf[nt][1] = *(const uint32_t*)(bp + 8);
            }
            #pragma unroll
            for (int nt = 0; nt < 4; nt++)
                asm volatile(
                    "mma.sync.aligned.m16n8k16.row.col.f32.bf16.bf16.f32 "
                    "{%0,%1,%2,%3}, {%4,%5,%6,%7}, {%8,%9}, {%0,%1,%2,%3};"
                    : "+f"(c[nt][0]), "+f"(c[nt][1]), "+f"(c[nt][2]), "+f"(c[nt][3])
                    : "r"(a[0]), "r"(a[1]), "r"(a[2]), "r"(a[3]),
                      "r"(bf[nt][0]), "r"(bf[nt][1]));
        }
        if (it + ST - 1 < NIT) ld_stage(Af, Bt, smem, m0, it + ST - 1, tid);
        asm volatile("cp.async.commit_group;" ::: "memory");
    }

    // epilogue: bias + sigmoid, fp32 out
    #pragma unroll
    for (int nt = 0; nt < 4; nt++) {
        const int col = wn * 32 + nt * 8 + lm4 * 2;
        const float b0 = __ldg(bias + col), b1 = __ldg(bias + col + 1);
        #pragma unroll
        for (int h = 0; h < 2; h++) {
            const int row = m0 + wm * 16 + ln4 + h * 8;
            const float x0 = c[nt][2 * h] + b0, x1 = c[nt][2 * h + 1] + b1;
            *(float2*)(H + (size_t)row * 64 + col) =
                make_float2(1.f / (1.f + __expf(-x0)), 1.f / (1.f + __expf(-x1)));
        }
    }
}

// ---- u = H2 @ Wd[0:64], v = H2 @ Wd[64:128]; Wd + H staged in smem ----
constexpr int HS = 68;
constexpr int SMEM_UV = 128 * 256 * 4 + 64 * HS * 4;   // 148480

__global__ void __launch_bounds__(256, 1)
k4_uv(const float* __restrict__ H2, const float* __restrict__ Wd,
      float* __restrict__ U, float* __restrict__ V) {
    extern __shared__ float sm[];
    float* Wds = sm;                           // [128][256]
    float* Hs  = sm + 128 * 256;               // [64][HS]
    const int tid = threadIdx.x, r0 = blockIdx.x * 64;

    for (int i = tid; i < 128 * 64; i += 256)
        *(float4*)(Wds + i * 4) = __ldg((const float4*)Wd + i);
    for (int i = tid; i < 64 * 16; i += 256) {
        const int r = i >> 4, cq = i & 15;
        *(float4*)(Hs + r * HS + cq * 4) = __ldg((const float4*)(H2 + (size_t)(r0 + r) * 64) + cq);
    }
    __syncthreads();

    const int cl = (tid & 7) * 4;
    #pragma unroll
    for (int b = 0; b < 2; b++) {
        const int rl = b * 32 + (tid >> 3);
        float au[32], av[32];
        #pragma unroll
        for (int q = 0; q < 32; q++) { au[q] = 0.f; av[q] = 0.f; }
        for (int j = 0; j < 64; j++) {
            const float hu = Hs[rl * HS + j];
            const float* wu = Wds + j * 256;
            const float* wv = Wds + (64 + j) * 256;
            #pragma unroll
            for (int q = 0; q < 8; q++) {
                const float4 a = *(const float4*)(wu + q * 32 + cl);
                au[4*q+0] = fmaf(hu, a.x, au[4*q+0]); au[4*q+1] = fmaf(hu, a.y, au[4*q+1]);
                au[4*q+2] = fmaf(hu, a.z, au[4*q+2]); au[4*q+3] = fmaf(hu, a.w, au[4*q+3]);
                const float4 v = *(const float4*)(wv + q * 32 + cl);
                av[4*q+0] = fmaf(hu, v.x, av[4*q+0]); av[4*q+1] = fmaf(hu, v.y, av[4*q+1]);
                av[4*q+2] = fmaf(hu, v.z, av[4*q+2]); av[4*q+3] = fmaf(hu, v.w, av[4*q+3]);
            }
        }
        float* uo = U + (size_t)(r0 + rl) * 256;
        float* vo = V + (size_t)(r0 + rl) * 256;
        #pragma unroll
        for (int q = 0; q < 8; q++) {
            *(float4*)(uo + q * 32 + cl) = make_float4(au[4*q], au[4*q+1], au[4*q+2], au[4*q+3]);
            *(float4*)(vo + q * 32 + cl) = make_float4(av[4*q], av[4*q+1], av[4*q+2], av[4*q+3]);
        }
    }
}

// ---- per-edge: softmax(relu(u[i]+v[j]+bd) @ Wo + bo) * mask ----
__global__ void __launch_bounds__(256)
edge_k(const int* __restrict__ eg, const int* __restrict__ msk,
       const float* __restrict__ U, const float* __restrict__ V,
       const float* __restrict__ bd, const float* __restrict__ Wo,
       const float* __restrict__ bo, float* __restrict__ out) {
    const int lane = threadIdx.x & 31;
    const int warp0 = (blockIdx.x * blockDim.x + threadIdx.x) >> 5;
    const int nwarp = (gridDim.x * blockDim.x) >> 5;
    const int c0 = lane * 8;

    float wd[8], bdv[8];
    #pragma unroll
    for (int q = 0; q < 4; q++) {
        const float4 w = __ldg((const float4*)Wo + lane * 4 + q);
        wd[2*q]   = w.x - w.y;
        wd[2*q+1] = w.z - w.w;
    }
    #pragma unroll
    for (int q = 0; q < 2; q++) {
        const float4 b = __ldg((const float4*)bd + lane * 2 + q);
        bdv[4*q+0] = b.x; bdv[4*q+1] = b.y; bdv[4*q+2] = b.z; bdv[4*q+3] = b.w;
    }
    const float dbo = __ldg(&bo[0]) - __ldg(&bo[1]);

    for (int e = warp0 * 2; e < Ee; e += nwarp * 2) {
        const int4 ij = __ldg((const int4*)(eg + 2 * e));
        const float4* u0 = (const float4*)(U + (size_t)ij.x * 256 + c0);
        const float4* v0 = (const float4*)(V + (size_t)ij.y * 256 + c0);
        const float4* u1 = (const float4*)(U + (size_t)ij.z * 256 + c0);
        const float4* v1 = (const float4*)(V + (size_t)ij.w * 256 + c0);
        float d0 = 0.f, d1 = 0.f;
        #pragma unroll
        for (int q = 0; q < 2; q++) {
            const float4 a0 = __ldg(u0 + q), b0v = __ldg(v0 + q);
            const float4 a1 = __ldg(u1 + q), b1v = __ldg(v1 + q);
            float s;
            s = fmaxf(a0.x + b0v.x + bdv[4*q+0], 0.f); d0 = fmaf(s, wd[4*q+0], d0);
            s = fmaxf(a0.y + b0v.y + bdv[4*q+1], 0.f); d0 = fmaf(s, wd[4*q+1], d0);
            s = fmaxf(a0.z + b0v.z + bdv[4*q+2], 0.f); d0 = fmaf(s, wd[4*q+2], d0);
            s = fmaxf(a0.w + b0v.w + bdv[4*q+3], 0.f); d0 = fmaf(s, wd[4*q+3], d0);
            s = fmaxf(a1.x + b1v.x + bdv[4*q+0], 0.f); d1 = fmaf(s, wd[4*q+0], d1);
            s = fmaxf(a1.y + b1v.y + bdv[4*q+1], 0.f); d1 = fmaf(s, wd[4*q+1], d1);
            s = fmaxf(a1.z + b1v.z + bdv[4*q+2], 0.f); d1 = fmaf(s, wd[4*q+2], d1);
            s = fmaxf(a1.w + b1v.w + bdv[4*q+3], 0.f); d1 = fmaf(s, wd[4*q+3], d1);
        }
        #pragma unroll
        for (int o = 16; o; o >>= 1) {
            d0 += __shfl_xor_sync(0xFFFFFFFFu, d0, o);
            d1 += __shfl_xor_sync(0xFFFFFFFFu, d1, o);
        }
        if (lane == 0) {
            const float p0 = 1.f / (1.f + __expf(-(d0 + dbo)));
            const float p1 = 1.f / (1.f + __expf(-(d1 + dbo)));
            const float m0 = (float)__ldg(&msk[e]);
            const float m1 = (float)__ldg(&msk[e + 1]);
            float4 o4;
            o4.x = p0 * m0; o4.y = (1.f - p0) * m0;
            o4.z = p1 * m1; o4.w = (1.f - p1) * m1;
            *(float4*)(out + 2 * e) = o4;
        }
    }
}

extern "C" void kernel_launch(void* const* d_in, const int* in_sizes, int n_in,
                              void* d_out, int out_size) {
    const float* X  = (const float*)d_in[0];
    const float* A  = (const float*)d_in[1];
    const int*   eg = (const int*)d_in[2];
    const int*   mk = (const int*)d_in[3];
    const float* W1 = (const float*)d_in[4];
    const float* b1 = (const float*)d_in[5];
    const float* W2 = (const float*)d_in[6];
    const float* b2 = (const float*)d_in[7];
    const float* Wd = (const float*)d_in[8];
    const float* bd = (const float*)d_in[9];
    const float* Wo = (const float*)d_in[10];
    const float* bo = (const float*)d_in[11];
    float* out = (float*)d_out;

    __nv_bfloat16 *Tbf;
    float *H1, *H2, *U, *V;
    cudaGetSymbolAddress((void**)&Tbf, g_Tbf);
    cudaGetSymbolAddress((void**)&H1, g_H1);
    cudaGetSymbolAddress((void**)&H2, g_H2);
    cudaGetSymbolAddress((void**)&U,  g_U);
    cudaGetSymbolAddress((void**)&V,  g_V);

    cudaFuncSetAttribute(gemm_f32a_sig, cudaFuncAttributeMaxDynamicSharedMemorySize, SMEM_DYN);
    cudaFuncSetAttribute(k4_uv, cudaFuncAttributeMaxDynamicSharedMemorySize, SMEM_UV);

    k_xw<128><<<Nn / 256, 256>>>(X, W1, Tbf);
    gemm_f32a_sig<<<Nn / MT, 256, SMEM_DYN>>>(A, Tbf, b1, H1);
    k_xw<64><<<Nn / 256, 256>>>(H1, W2, Tbf);
    gemm_f32a_sig<<<Nn / MT, 256, SMEM_DYN>>>(A, Tbf, b2, H2);
    k4_uv<<<Nn / 64, 256, SMEM_UV>>>(H2, Wd, U, V);
    edge_k<<<592, 256>>>(eg, mk, U, V, bd, Wo, bo, out);
}

// round 17
// speedup vs baseline: 2.5093x; 1.0672x over previous
#include <cuda_runtime.h>
#include <cuda_bf16.h>
#include <cstdint>

constexpr int Nn = 16384, Ee = 524288;

// ---- scratch (device globals; allocs forbidden) ----
__device__ __nv_bfloat16 g_Tbf[64 * Nn];     // (X@W)^T in bf16, [64][Nn] K-major
__device__ float g_H1[Nn * 64];
__device__ float g_H2[Nn * 64];
__device__ float g_U[Nn * 256];
__device__ float g_V[Nn * 256];

// ---- Tbf[n0+n][r] = bf16( sum_k X[r][k] * W[k][n0+n] ), 32 cols per block ----
template <int K>
__global__ void __launch_bounds__(256)
k_xw(const float* __restrict__ X, const float* __restrict__ W, __nv_bfloat16* __restrict__ Tbf) {
    __shared__ float Ws[K * 32];
    const int tid = threadIdx.x;
    const int n0 = blockIdx.y * 32;
    for (int i = tid; i < K * 32; i += 256)
        Ws[i] = W[(i >> 5) * 64 + n0 + (i & 31)];
    __syncthreads();
    const int r = blockIdx.x * 256 + tid;
    float acc[32];
    #pragma unroll
    for (int n = 0; n < 32; n++) acc[n] = 0.f;
    const float4* xr = (const float4*)(X + (size_t)r * K);
    #pragma unroll 4
    for (int k4 = 0; k4 < K / 4; k4++) {
        float4 xv = __ldg(xr + k4);
        float xs[4] = {xv.x, xv.y, xv.z, xv.w};
        #pragma unroll
        for (int u = 0; u < 4; u++) {
            const float* wk = &Ws[(k4 * 4 + u) * 32];
            #pragma unroll
            for (int n = 0; n < 32; n++) acc[n] = fmaf(xs[u], wk[n], acc[n]);
        }
    }
    #pragma unroll
    for (int n = 0; n < 32; n++) Tbf[(size_t)(n0 + n) * Nn + r] = __float2bfloat16(acc[n]);
}

// ---- GEMM: H = sigmoid(A_fp32 @ Tbf^T + bias) ----
// R12-proven config: MT=128, 256 threads (8 warps 4Mx2N), ST=4 cp.async fp32-A,
// in-register cvt to bf16. Micro-fix: next-stage loads issued BEFORE compute.
constexpr int MT = 128, KC = 64, ST = 4, NIT = Nn / KC;
constexpr int ASf = 72;                       // A smem row stride (floats) -> 288 B
constexpr int BSe = 72;                       // B smem row stride (bf16)   -> 144 B
constexpr int A_BYTES = 128 * ASf * 4;        // 36864
constexpr int B_BYTES = 64 * BSe * 2;         // 9216
constexpr int STG_B = A_BYTES + B_BYTES;      // 46080
constexpr int SMEM_DYN = ST * STG_B;          // 184320

__device__ __forceinline__ uint32_t cvt2(float2 p) {
    uint32_t r;
    asm("cvt.rn.bf16x2.f32 %0, %1, %2;" : "=r"(r) : "f"(p.y), "f"(p.x));
    return r;
}

__device__ __forceinline__ void ld_stage(const float* __restrict__ Af,
                                         const __nv_bfloat16* __restrict__ Bt,
                                         char* sm, int m0, int it, int tid) {
    const int k0 = it * KC;
    const uint32_t sb = (uint32_t)__cvta_generic_to_shared(sm + (it % ST) * STG_B);
    #pragma unroll
    for (int i = 0; i < 10; i++) {
        const int f = i * 256 + tid;          // 16B chunks: A 2048, B 512
        uint32_t dst;
        const void* src;
        if (f < 2048) {
            const int r = f >> 4, c = f & 15;
            src = Af + (size_t)(m0 + r) * Nn + k0 + c * 4;
            dst = sb + (uint32_t)(r * 288 + c * 16);
        } else {
            const int f2 = f - 2048;
            const int n = f2 >> 3, c = f2 & 7;
            src = Bt + (size_t)n * Nn + k0 + c * 8;
            dst = sb + (uint32_t)(A_BYTES + n * 144 + c * 16);
        }
        asm volatile("cp.async.cg.shared.global [%0], [%1], 16;" :: "r"(dst), "l"(src) : "memory");
    }
}

__global__ void __launch_bounds__(256, 1)
gemm_f32a_sig(const float* __restrict__ Af, const __nv_bfloat16* __restrict__ Bt,
              const float* __restrict__ bias, float* __restrict__ H) {
    extern __shared__ char smem[];
    const int tid = threadIdx.x, wid = tid >> 5, lane = tid & 31;
    const int wm = wid >> 1, wn = wid & 1;    // warps 4(M) x 2(N)
    const int ln4 = lane >> 2, lm4 = lane & 3;
    const int m0 = blockIdx.x * MT;

    float c[2][4][4];
    #pragma unroll
    for (int a = 0; a < 2; a++)
        #pragma unroll
        for (int b = 0; b < 4; b++)
            #pragma unroll
            for (int q = 0; q < 4; q++) c[a][b][q] = 0.f;

    #pragma unroll
    for (int s = 0; s < ST - 1; s++) {
        ld_stage(Af, Bt, smem, m0, s, tid);
        asm volatile("cp.async.commit_group;" ::: "memory");
    }

    for (int it = 0; it < NIT; it++) {
        asm volatile("cp.async.wait_group 2;" ::: "memory");
        __syncthreads();
        // issue next-stage loads FIRST: target buffer (it+3)%4 == (it-1)%4 was
        // fully consumed before the sync above released this iteration.
        if (it + ST - 1 < NIT) ld_stage(Af, Bt, smem, m0, it + ST - 1, tid);
        asm volatile("cp.async.commit_group;" ::: "memory");

        const float* Asm = (const float*)(smem + (it % ST) * STG_B);
        const __nv_bfloat16* Bsm = (const __nv_bfloat16*)(smem + (it % ST) * STG_B + A_BYTES);
        #pragma unroll
        for (int ks = 0; ks < 4; ks++) {
            const int kb = ks * 16 + lm4 * 2;
            uint32_t a[2][4], bf[4][2];
            #pragma unroll
            for (int mt = 0; mt < 2; mt++) {
                const float* ap = Asm + (wm * 32 + mt * 16 + ln4) * ASf + kb;
                a[mt][0] = cvt2(*(const float2*)ap);
                a[mt][1] = cvt2(*(const float2*)(ap + 8 * ASf));
                a[mt][2] = cvt2(*(const float2*)(ap + 8));
                a[mt][3] = cvt2(*(const float2*)(ap + 8 * ASf + 8));
            }
            #pragma unroll
            for (int nt = 0; nt < 4; nt++) {
                const __nv_bfloat16* bp = Bsm + (wn * 32 + nt * 8 + ln4) * BSe + kb;
                bf[nt][0] = *(const uint32_t*)bp;
                bf[nt][1] = *(const uint32_t*)(bp + 8);
            }
            #pragma unroll
            for (int mt = 0; mt < 2; mt++)
                #pragma unroll
                for (int nt = 0; nt < 4; nt++)
                    asm volatile(
                        "mma.sync.aligned.m16n8k16.row.col.f32.bf16.bf16.f32 "
                        "{%0,%1,%2,%3}, {%4,%5,%6,%7}, {%8,%9}, {%0,%1,%2,%3};"
                        : "+f"(c[mt][nt][0]), "+f"(c[mt][nt][1]),
                          "+f"(c[mt][nt][2]), "+f"(c[mt][nt][3])
                        : "r"(a[mt][0]), "r"(a[mt][1]), "r"(a[mt][2]), "r"(a[mt][3]),
                          "r"(bf[nt][0]), "r"(bf[nt][1]));
        }
    }

    // epilogue: bias + sigmoid, fp32 out
    #pragma unroll
    for (int mt = 0; mt < 2; mt++)
        #pragma unroll
        for (int nt = 0; nt < 4; nt++) {
            const int col = wn * 32 + nt * 8 + lm4 * 2;
            const float b0 = __ldg(bias + col), b1 = __ldg(bias + col + 1);
            #pragma unroll
            for (int h = 0; h < 2; h++) {
                const int row = m0 + wm * 32 + mt * 16 + ln4 + h * 8;
                const float x0 = c[mt][nt][2 * h] + b0, x1 = c[mt][nt][2 * h + 1] + b1;
                *(float2*)(H + (size_t)row * 64 + col) =
                    make_float2(1.f / (1.f + __expf(-x0)), 1.f / (1.f + __expf(-x1)));
            }
        }
}

// ---- u = H2 @ Wd[0:64], v = H2 @ Wd[64:128]; Wd + H staged in smem ----
constexpr int HS = 68;
constexpr int SMEM_UV = 128 * 256 * 4 + 64 * HS * 4;   // 148480

__global__ void __launch_bounds__(256, 1)
k4_uv(const float* __restrict__ H2, const float* __restrict__ Wd,
      float* __restrict__ U, float* __restrict__ V) {
    extern __shared__ float sm[];
    float* Wds = sm;                           // [128][256]
    float* Hs  = sm + 128 * 256;               // [64][HS]
    const int tid = threadIdx.x, r0 = blockIdx.x * 64;

    for (int i = tid; i < 128 * 64; i += 256)
        *(float4*)(Wds + i * 4) = __ldg((const float4*)Wd + i);
    for (int i = tid; i < 64 * 16; i += 256) {
        const int r = i >> 4, cq = i & 15;
        *(float4*)(Hs + r * HS + cq * 4) = __ldg((const float4*)(H2 + (size_t)(r0 + r) * 64) + cq);
    }
    __syncthreads();

    const int cl = (tid & 7) * 4;
    #pragma unroll
    for (int b = 0; b < 2; b++) {
        const int rl = b * 32 + (tid >> 3);
        float au[32], av[32];
        #pragma unroll
        for (int q = 0; q < 32; q++) { au[q] = 0.f; av[q] = 0.f; }
        for (int j = 0; j < 64; j++) {
            const float hu = Hs[rl * HS + j];
            const float* wu = Wds + j * 256;
            const float* wv = Wds + (64 + j) * 256;
            #pragma unroll
            for (int q = 0; q < 8; q++) {
                const float4 a = *(const float4*)(wu + q * 32 + cl);
                au[4*q+0] = fmaf(hu, a.x, au[4*q+0]); au[4*q+1] = fmaf(hu, a.y, au[4*q+1]);
                au[4*q+2] = fmaf(hu, a.z, au[4*q+2]); au[4*q+3] = fmaf(hu, a.w, au[4*q+3]);
                const float4 v = *(const float4*)(wv + q * 32 + cl);
                av[4*q+0] = fmaf(hu, v.x, av[4*q+0]); av[4*q+1] = fmaf(hu, v.y, av[4*q+1]);
                av[4*q+2] = fmaf(hu, v.z, av[4*q+2]); av[4*q+3] = fmaf(hu, v.w, av[4*q+3]);
            }
        }
        float* uo = U + (size_t)(r0 + rl) * 256;
        float* vo = V + (size_t)(r0 + rl) * 256;
        #pragma unroll
        for (int q = 0; q < 8; q++) {
            *(float4*)(uo + q * 32 + cl) = make_float4(au[4*q], au[4*q+1], au[4*q+2], au[4*q+3]);
            *(float4*)(vo + q * 32 + cl) = make_float4(av[4*q], av[4*q+1], av[4*q+2], av[4*q+3]);
        }
    }
}

// ---- per-edge: softmax(relu(u[i]+v[j]+bd) @ Wo + bo) * mask ----
__global__ void __launch_bounds__(256)
edge_k(const int* __restrict__ eg, const int* __restrict__ msk,
       const float* __restrict__ U, const float* __restrict__ V,
       const float* __restrict__ bd, const float* __restrict__ Wo,
       const float* __restrict__ bo, float* __restrict__ out) {
    const int lane = threadIdx.x & 31;
    const int warp0 = (blockIdx.x * blockDim.x + threadIdx.x) >> 5;
    const int nwarp = (gridDim.x * blockDim.x) >> 5;
    const int c0 = lane * 8;

    float wd[8], bdv[8];
    #pragma unroll
    for (int q = 0; q < 4; q++) {
        const float4 w = __ldg((const float4*)Wo + lane * 4 + q);
        wd[2*q]   = w.x - w.y;
        wd[2*q+1] = w.z - w.w;
    }
    #pragma unroll
    for (int q = 0; q < 2; q++) {
        const float4 b = __ldg((const float4*)bd + lane * 2 + q);
        bdv[4*q+0] = b.x; bdv[4*q+1] = b.y; bdv[4*q+2] = b.z; bdv[4*q+3] = b.w;
    }
    const float dbo = __ldg(&bo[0]) - __ldg(&bo[1]);

    for (int e = warp0 * 2; e < Ee; e += nwarp * 2) {
        const int4 ij = __ldg((const int4*)(eg + 2 * e));
        const float4* u0 = (const float4*)(U + (size_t)ij.x * 256 + c0);
        const float4* v0 = (const float4*)(V + (size_t)ij.y * 256 + c0);
        const float4* u1 = (const float4*)(U + (size_t)ij.z * 256 + c0);
        const float4* v1 = (const float4*)(V + (size_t)ij.w * 256 + c0);
        float d0 = 0.f, d1 = 0.f;
        #pragma unroll
        for (int q = 0; q < 2; q++) {
            const float4 a0 = __ldg(u0 + q), b0v = __ldg(v0 + q);
            const float4 a1 = __ldg(u1 + q), b1v = __ldg(v1 + q);
            float s;
            s = fmaxf(a0.x + b0v.x + bdv[4*q+0], 0.f); d0 = fmaf(s, wd[4*q+0], d0);
            s = fmaxf(a0.y + b0v.y + bdv[4*q+1], 0.f); d0 = fmaf(s, wd[4*q+1], d0);
            s = fmaxf(a0.z + b0v.z + bdv[4*q+2], 0.f); d0 = fmaf(s, wd[4*q+2], d0);
            s = fmaxf(a0.w + b0v.w + bdv[4*q+3], 0.f); d0 = fmaf(s, wd[4*q+3], d0);
            s = fmaxf(a1.x + b1v.x + bdv[4*q+0], 0.f); d1 = fmaf(s, wd[4*q+0], d1);
            s = fmaxf(a1.y + b1v.y + bdv[4*q+1], 0.f); d1 = fmaf(s, wd[4*q+1], d1);
            s = fmaxf(a1.z + b1v.z + bdv[4*q+2], 0.f); d1 = fmaf(s, wd[4*q+2], d1);
            s = fmaxf(a1.w + b1v.w + bdv[4*q+3], 0.f); d1 = fmaf(s, wd[4*q+3], d1);
        }
        #pragma unroll
        for (int o = 16; o; o >>= 1) {
            d0 += __shfl_xor_sync(0xFFFFFFFFu, d0, o);
            d1 += __shfl_xor_sync(0xFFFFFFFFu, d1, o);
        }
        if (lane == 0) {
            const float p0 = 1.f / (1.f + __expf(-(d0 + dbo)));
            const float p1 = 1.f / (1.f + __expf(-(d1 + dbo)));
            const float m0 = (float)__ldg(&msk[e]);
            const float m1 = (float)__ldg(&msk[e + 1]);
            float4 o4;
            o4.x = p0 * m0; o4.y = (1.f - p0) * m0;
            o4.z = p1 * m1; o4.w = (1.f - p1) * m1;
            *(float4*)(out + 2 * e) = o4;
        }
    }
}

extern "C" void kernel_launch(void* const* d_in, const int* in_sizes, int n_in,
                              void* d_out, int out_size) {
    const float* X  = (const float*)d_in[0];
    const float* A  = (const float*)d_in[1];
    const int*   eg = (const int*)d_in[2];
    const int*   mk = (const int*)d_in[3];
    const float* W1 = (const float*)d_in[4];
    const float* b1 = (const float*)d_in[5];
    const float* W2 = (const float*)d_in[6];
    const float* b2 = (const float*)d_in[7];
    const float* Wd = (const float*)d_in[8];
    const float* bd = (const float*)d_in[9];
    const float* Wo = (const float*)d_in[10];
    const float* bo = (const float*)d_in[11];
    float* out = (float*)d_out;

    __nv_bfloat16 *Tbf;
    float *H1, *H2, *U, *V;
    cudaGetSymbolAddress((void**)&Tbf, g_Tbf);
    cudaGetSymbolAddress((void**)&H1, g_H1);
    cudaGetSymbolAddress((void**)&H2, g_H2);
    cudaGetSymbolAddress((void**)&U,  g_U);
    cudaGetSymbolAddress((void**)&V,  g_V);

    cudaFuncSetAttribute(gemm_f32a_sig, cudaFuncAttributeMaxDynamicSharedMemorySize, SMEM_DYN);
    cudaFuncSetAttribute(k4_uv, cudaFuncAttributeMaxDynamicSharedMemorySize, SMEM_UV);

    dim3 gx(Nn / 256, 2);
    k_xw<128><<<gx, 256>>>(X, W1, Tbf);
    gemm_f32a_sig<<<Nn / MT, 256, SMEM_DYN>>>(A, Tbf, b1, H1);
    k_xw<64><<<gx, 256>>>(H1, W2, Tbf);
    gemm_f32a_sig<<<Nn / MT, 256, SMEM_DYN>>>(A, Tbf, b2, H2);
    k4_uv<<<Nn / 64, 256, SMEM_UV>>>(H2, Wd, U, V);
    edge_k<<<592, 256>>>(eg, mk, U, V, bd, Wo, bo, out);
}